// round 11
// baseline (speedup 1.0000x reference)
#include <cuda_runtime.h>
#include <cuda_fp16.h>
#include <cstdint>

// ---------------- model constants ----------------
#define BSZ      512
#define NCH      129
#define NT       250
#define DINNER   256
#define DSTATE   16
#define NHEADS   4
#define CONVDIM  288
#define DPROJ    548
#define EPSV     1e-5f
#define ROWH     544        // gz(256)+xBC raw(288) fp16 per row

// GEMM tiling
#define TM     128
#define TN     144          // 576 = 4 chunks of 144
#define TK     128
#define NJC    4
#define NKK    8
#define PITCHB 272
#define SPITCH 148

// ---------------- device scratch ----------------
__device__ float g_W[DPROJ * NCH];
__device__ float g_bias[DPROJ];
__device__ float g_v[DINNER];
__device__ __align__(16) __half g_zx[(size_t)BSZ * NT * ROWH];   // ~139 MB
__device__ __align__(16) float g_dtA[(size_t)BSZ * NT * 8];      // dt/dA pairs, 4 MB
__device__ __align__(16) __half g_gout[(size_t)BSZ * NT * 256];  // gated outputs, 65 MB
__device__ __align__(16) __half g_Wh[NJC * TN * TK];
__device__ float g_Wcol[576];
__device__ float g_biasP[576];

// ---------------- GEMM smem layout (bytes) ----------------
// Stage region (epilogue fp32 staging) occupies [0, 75776).
// Constants MUST live beyond it (R10 bug: they overlapped the stage).
#define SM_AH    0                      // 128*272 = 34816
#define SM_BH    34816                  // 144*272 = 39168 -> ends 73984
#define STAGE_B  75776                  // 128*148*4
#define SM_X128  75776                  // 128 fp32  (beyond stage)
#define SM_W128  76288                  // 144 fp32
#define SM_BIAS  76864                  // 144 fp32
#define SMEM_SZ  77440

// ---------------- packed f32x2 helpers ----------------
typedef unsigned long long ull;
__device__ __forceinline__ ull dup2(float v) {
    ull r; asm("mov.b64 %0, {%1, %1};" : "=l"(r) : "f"(v)); return r;
}
__device__ __forceinline__ ull pack2(float lo, float hi) {
    ull r; asm("mov.b64 %0, {%1, %2};" : "=l"(r) : "f"(lo), "f"(hi)); return r;
}
__device__ __forceinline__ ull ffma2(ull a, ull b, ull c) {
    ull d; asm("fma.rn.f32x2 %0, %1, %2, %3;" : "=l"(d) : "l"(a), "l"(b), "l"(c)); return d;
}
__device__ __forceinline__ ull fmul2(ull a, ull b) {
    ull d; asm("mul.rn.f32x2 %0, %1, %2;" : "=l"(d) : "l"(a), "l"(b)); return d;
}
__device__ __forceinline__ float2 unpk2(ull v) {
    float2 f; asm("mov.b64 {%0, %1}, %2;" : "=f"(f.x), "=f"(f.y) : "l"(v)); return f;
}

// ---------------- mma / ldmatrix (base sm_103 PTX) ----------------
__device__ __forceinline__ void mma16816(float* d, const uint32_t* a, const uint32_t* b) {
    asm volatile(
        "mma.sync.aligned.m16n8k16.row.col.f32.f16.f16.f32 "
        "{%0,%1,%2,%3}, {%4,%5,%6,%7}, {%8,%9}, {%0,%1,%2,%3};"
        : "+f"(d[0]), "+f"(d[1]), "+f"(d[2]), "+f"(d[3])
        : "r"(a[0]), "r"(a[1]), "r"(a[2]), "r"(a[3]), "r"(b[0]), "r"(b[1]));
}
__device__ __forceinline__ void ldsm4(uint32_t* r, uint32_t addr) {
    asm volatile("ldmatrix.sync.aligned.m8n8.x4.shared.b16 {%0,%1,%2,%3}, [%4];"
        : "=r"(r[0]), "=r"(r[1]), "=r"(r[2]), "=r"(r[3]) : "r"(addr));
}
__device__ __forceinline__ uint32_t smem_u32(const void* p) {
    uint32_t a;
    asm("{ .reg .u64 t; cvta.to.shared.u64 t, %1; cvt.u32.u64 %0, t; }" : "=r"(a) : "l"(p));
    return a;
}

// =====================================================================
// prep1: fused weights
// =====================================================================
__global__ void prep1_kernel(const float* __restrict__ in_proj_w,
                             const float* __restrict__ mixer_w,
                             const float* __restrict__ mixer_b,
                             const float* __restrict__ out_proj_w,
                             const float* __restrict__ head_w) {
    int idx = blockIdx.x * blockDim.x + threadIdx.x;
    const int NW = DPROJ * NCH;
    if (idx < NW) {
        int j = idx / NCH, c = idx - j * NCH;
        float a0 = 0.f, a1 = 0.f, a2 = 0.f, a3 = 0.f;
        #pragma unroll 8
        for (int d = 0; d < 128; d += 4) {
            a0 = fmaf(in_proj_w[j * 128 + d + 0], mixer_w[(d + 0) * NCH + c], a0);
            a1 = fmaf(in_proj_w[j * 128 + d + 1], mixer_w[(d + 1) * NCH + c], a1);
            a2 = fmaf(in_proj_w[j * 128 + d + 2], mixer_w[(d + 2) * NCH + c], a2);
            a3 = fmaf(in_proj_w[j * 128 + d + 3], mixer_w[(d + 3) * NCH + c], a3);
        }
        g_W[idx] = (a0 + a1) + (a2 + a3);
    } else if (idx < NW + DPROJ) {
        int j = idx - NW;
        float acc = 0.f;
        #pragma unroll 4
        for (int d = 0; d < 128; d++)
            acc = fmaf(in_proj_w[j * 128 + d], mixer_b[d], acc);
        g_bias[j] = acc;
    } else if (idx < NW + DPROJ + DINNER) {
        int i = idx - NW - DPROJ;
        float acc = 0.f;
        #pragma unroll 4
        for (int d = 0; d < 128; d++)
            acc = fmaf(out_proj_w[d * DINNER + i], head_w[d], acc);
        g_v[i] = acc;
    }
}

// =====================================================================
// prep2: W (k<128) -> fp16 chunk tiles [jc][n(144)][k(128)]
// =====================================================================
__global__ void prep2_kernel() {
    int idx = blockIdx.x * blockDim.x + threadIdx.x;
    const int NH = NJC * TN * TK;            // 73728
    if (idx < NH) {
        int k = idx & 127;
        int t = idx >> 7;
        int n = t % TN;
        int jc = t / TN;
        int j = jc * TN + n;
        float val = (j < DPROJ) ? g_W[j * NCH + k] : 0.f;
        g_Wh[idx] = __float2half(val);
    } else if (idx < NH + 576) {
        int j = idx - NH;
        g_Wcol[j] = (j < DPROJ) ? g_W[j * NCH + 128] : 0.f;
    } else if (idx < NH + 1152) {
        int j = idx - NH - 576;
        g_biasP[j] = (j < DPROJ) ? g_bias[j] : 0.f;
    }
}

// =====================================================================
// gemm_mma: single-pass fp16 GEMM, TN=144, epilogue applies silu(z)
//   and softplus(dt)/exp(dt*A); writes fp16 gz/xBC + fp32 dt/dA
// =====================================================================
__global__ void __launch_bounds__(256, 2)
gemm_mma(const float* __restrict__ x,
         const float* __restrict__ dt_bias,
         const float* __restrict__ A_log) {
    extern __shared__ __align__(16) unsigned char sm[];
    const uint32_t sbase = smem_u32(sm);
    const int tid = threadIdx.x;
    const int wid = tid >> 5, lane = tid & 31;
    const int gid = lane >> 2, tig = lane & 3;
    const int tt = blockIdx.x, jc = blockIdx.y, b = blockIdx.z;
    const int t0 = tt * TM;

    // ---- B tile: fp16 W chunk (256 B/row -> pitch 272)
    {
        const unsigned char* src = (const unsigned char*)(g_Wh + (size_t)jc * (TN * TK));
        for (int i = tid; i < TN * 16; i += 256) {
            int n = i >> 4, q = i & 15;
            *(uint4*)(sm + SM_BH + n * PITCHB + q * 16) = *(const uint4*)(src + n * 256 + q * 16);
        }
    }
    // ---- A tile: x fp32 -> fp16 pairs
    {
        const float* xb = x + (size_t)b * (NCH * NT);
        for (int i = tid; i < 64 * TM; i += 256) {
            int cp = i >> 7, m = i & (TM - 1);
            int t = t0 + m;
            int c0 = 2 * cp;
            float v0 = (t < NT) ? xb[(size_t)c0 * NT + t] : 0.f;
            float v1 = (t < NT) ? xb[(size_t)(c0 + 1) * NT + t] : 0.f;
            uint32_t off = (uint32_t)m * PITCHB + (uint32_t)cp * 4;
            *(__half2*)(sm + SM_AH + off) = __half2{__float2half(v0), __float2half(v1)};
        }
    }
    // ---- epilogue constants (region beyond the stage — R10 fix)
    if (tid < 128) {
        int t = t0 + tid;
        const float* xb = x + (size_t)b * (NCH * NT);
        *(float*)(sm + SM_X128 + tid * 4) = (t < NT) ? xb[(size_t)128 * NT + t] : 0.f;
    }
    for (int i = tid; i < TN; i += 256) {
        *(float*)(sm + SM_W128 + i * 4) = g_Wcol[jc * TN + i];
        *(float*)(sm + SM_BIAS + i * 4) = g_biasP[jc * TN + i];
    }
    __syncthreads();

    // ---- mainloop: 8 k-steps, 18 n-frags ----
    float acc[18][4];
    #pragma unroll
    for (int ni = 0; ni < 18; ni++)
        #pragma unroll
        for (int q = 0; q < 4; q++) acc[ni][q] = 0.f;

    const uint32_t aOff = (uint32_t)(wid * 16 + (lane & 15)) * PITCHB + (uint32_t)(lane >> 4) * 16;
    const uint32_t bOff = (uint32_t)(lane & 15) * PITCHB + (uint32_t)(lane >> 4) * 16;

    const uint32_t Ah = sbase + SM_AH + aOff;
    const uint32_t Bb = sbase + SM_BH + bOff;

    #pragma unroll
    for (int kk = 0; kk < NKK; kk++) {
        uint32_t ah[4];
        ldsm4(ah, Ah + kk * 32);
        #pragma unroll
        for (int q = 0; q < 9; q++) {
            uint32_t bb[4];
            ldsm4(bb, Bb + (uint32_t)(q * 16) * PITCHB + kk * 32);
            uint32_t f0[2] = { bb[0], bb[2] };
            uint32_t f1[2] = { bb[1], bb[3] };
            mma16816(acc[2 * q],     ah, f0);
            mma16816(acc[2 * q + 1], ah, f1);
        }
    }

    // ---- stage accumulators to smem [0, 75776) ----
    __syncthreads();
    float* stage = (float*)sm;              // 128 x 148 fp32
    {
        int r = wid * 16 + gid;
        #pragma unroll
        for (int ni = 0; ni < 18; ni++) {
            int c = ni * 8 + 2 * tig;
            *(float2*)(stage + r * SPITCH + c) = make_float2(acc[ni][0], acc[ni][1]);
            *(float2*)(stage + (r + 8) * SPITCH + c) = make_float2(acc[ni][2], acc[ni][3]);
        }
    }
    __syncthreads();

    // ---- epilogue: k=128 fixup + bias; route by column class ----
    const float* xs128 = (const float*)(sm + SM_X128);
    const float* sW = (const float*)(sm + SM_W128);
    const float* sBs = (const float*)(sm + SM_BIAS);
    for (int i = tid; i < TM * (TN / 4); i += 256) {
        int row = i / (TN / 4), q = i % (TN / 4);
        int t = t0 + row;
        int j = jc * TN + 4 * q;
        if (t >= NT) continue;
        const float* sp = stage + row * SPITCH + 4 * q;
        float xk = xs128[row];
        float o0 = fmaf(xk, sW[4 * q + 0], sp[0] + sBs[4 * q + 0]);
        float o1 = fmaf(xk, sW[4 * q + 1], sp[1] + sBs[4 * q + 1]);
        float o2 = fmaf(xk, sW[4 * q + 2], sp[2] + sBs[4 * q + 2]);
        float o3 = fmaf(xk, sW[4 * q + 3], sp[3] + sBs[4 * q + 3]);
        if (j + 3 < 256) {
            // z block: apply silu, store gz fp16
            o0 = __fdividef(o0, 1.f + __expf(-o0));
            o1 = __fdividef(o1, 1.f + __expf(-o1));
            o2 = __fdividef(o2, 1.f + __expf(-o2));
            o3 = __fdividef(o3, 1.f + __expf(-o3));
            __half2 ha = __floats2half2_rn(o0, o1);
            __half2 hb = __floats2half2_rn(o2, o3);
            uint2 pk = { *(uint32_t*)&ha, *(uint32_t*)&hb };
            *(uint2*)(g_zx + ((size_t)b * NT + t) * ROWH + j) = pk;
        } else if (j + 3 < 544) {
            // raw xBC fp16
            __half2 ha = __floats2half2_rn(o0, o1);
            __half2 hb = __floats2half2_rn(o2, o3);
            uint2 pk = { *(uint32_t*)&ha, *(uint32_t*)&hb };
            *(uint2*)(g_zx + ((size_t)b * NT + t) * ROWH + j) = pk;
        } else if (j == 544) {
            // dt block: softplus + dA = exp(dt * -exp(A_log))
            float ov[4] = { o0, o1, o2, o3 };
            float* dst = g_dtA + ((size_t)b * NT + t) * 8;
            float4 lo, hi;
            float r0 = ov[0] + dt_bias[0];
            float d0 = (r0 > 15.f) ? r0 : __logf(1.f + __expf(r0));
            lo.x = d0; lo.y = __expf(d0 * -__expf(A_log[0]));
            float r1 = ov[1] + dt_bias[1];
            float d1 = (r1 > 15.f) ? r1 : __logf(1.f + __expf(r1));
            lo.z = d1; lo.w = __expf(d1 * -__expf(A_log[1]));
            float r2 = ov[2] + dt_bias[2];
            float d2 = (r2 > 15.f) ? r2 : __logf(1.f + __expf(r2));
            hi.x = d2; hi.y = __expf(d2 * -__expf(A_log[2]));
            float r3 = ov[3] + dt_bias[3];
            float d3 = (r3 > 15.f) ? r3 : __logf(1.f + __expf(r3));
            hi.z = d3; hi.w = __expf(d3 * -__expf(A_log[3]));
            *(float4*)(dst) = lo;
            *(float4*)(dst + 4) = hi;
        }
        // j >= 548: padding, skip
    }
}

// =====================================================================
// scan: 160 threads, minimal critical path — no reduce, no z-gate MUFU,
//   no dt work. Producers conv B/C; scan threads conv x + state + store g.
// =====================================================================
__global__ void __launch_bounds__(160, 4)
scan_kernel(const float* __restrict__ conv_w, const float* __restrict__ conv_b,
            const float* __restrict__ Dp) {
    const int b = blockIdx.x;
    const int tid = threadIdx.x;
    const int c0 = 2 * tid;
    const int h = tid >> 5;

    __shared__ __align__(8) float2 sB2[2][DSTATE];
    __shared__ __align__(8) float2 sC2[2][DSTATE];

    const bool isConv = (tid < 144);
    const bool isScan = (tid < 128);

    ull wk0 = 0, wk1 = 0, wk2_ = 0, wk3 = 0, cb2 = 0;
    if (isConv) {
        wk0 = pack2(conv_w[c0 * 4 + 0], conv_w[(c0 + 1) * 4 + 0]);
        wk1 = pack2(conv_w[c0 * 4 + 1], conv_w[(c0 + 1) * 4 + 1]);
        wk2_ = pack2(conv_w[c0 * 4 + 2], conv_w[(c0 + 1) * 4 + 2]);
        wk3 = pack2(conv_w[c0 * 4 + 3], conv_w[(c0 + 1) * 4 + 3]);
        cb2 = pack2(conv_b[c0], conv_b[c0 + 1]);
    }
    ull h1 = 0ULL, h2 = 0ULL, h3 = 0ULL;

    ull D2 = 0ULL;
    if (isScan) D2 = dup2(Dp[h]);

    ull s2[DSTATE];
    #pragma unroll
    for (int n = 0; n < DSTATE; n++) s2[n] = 0ULL;

    const __half* zx = g_zx + (size_t)b * NT * ROWH;
    const float* dtp = g_dtA + (size_t)b * NT * 8;
    __half* gout = g_gout + (size_t)b * NT * 256;

    // prefetch t=0
    __half2 rawh = __half2{}, gzh = __half2{};
    float2 dtA = make_float2(0.f, 0.f);
    if (isConv) rawh = *(const __half2*)(zx + 256 + c0);
    if (isScan) {
        gzh = *(const __half2*)(zx + c0);
        dtA = *(const float2*)(dtp + 2 * h);
    }

    for (int t = 0; t < NT; t++) {
        const int buf = t & 1;

        // ---- conv + silu ----
        float cs0 = 0.f, cs1 = 0.f;
        if (isConv) {
            float2 fr = __half22float2(rawh);
            ull r2 = pack2(fr.x, fr.y);
            ull cv2 = ffma2(wk3, r2, ffma2(wk2_, h1, ffma2(wk1, h2, ffma2(wk0, h3, cb2))));
            h3 = h2; h2 = h1; h1 = r2;
            float2 cv = unpk2(cv2);
            cs0 = __fdividef(cv.x, 1.f + __expf(-cv.x));
            cs1 = __fdividef(cv.y, 1.f + __expf(-cv.y));
            if (tid >= 128) {
                if (tid < 136) {
                    int k = 2 * (tid - 128);
                    sB2[buf][k]     = make_float2(cs0, cs0);
                    sB2[buf][k + 1] = make_float2(cs1, cs1);
                } else {
                    int k = 2 * (tid - 136);
                    sC2[buf][k]     = make_float2(cs0, cs0);
                    sC2[buf][k + 1] = make_float2(cs1, cs1);
                }
            }
        }

        // ---- prefetch t+1 ----
        __half2 nrawh = __half2{}, ngzh = __half2{};
        float2 ndtA = make_float2(0.f, 0.f);
        if (t + 1 < NT) {
            const __half* rn = zx + (size_t)(t + 1) * ROWH;
            if (isConv) nrawh = *(const __half2*)(rn + 256 + c0);
            if (isScan) {
                ngzh = *(const __half2*)(rn + c0);
                ndtA = *(const float2*)(dtp + (size_t)(t + 1) * 8 + 2 * h);
            }
        }
        __syncthreads();

        // ---- state update + gate + store ----
        if (isScan) {
            ull dA2 = dup2(dtA.y);
            ull dx2 = pack2(dtA.x * cs0, dtA.x * cs1);
            ull ya = fmul2(D2, pack2(cs0, cs1));
            ull yb = 0ULL;
            #pragma unroll
            for (int n = 0; n < DSTATE; n += 2) {
                s2[n]     = ffma2(s2[n],     dA2, fmul2(dx2, *(const ull*)&sB2[buf][n]));
                ya        = ffma2(s2[n],     *(const ull*)&sC2[buf][n], ya);
                s2[n + 1] = ffma2(s2[n + 1], dA2, fmul2(dx2, *(const ull*)&sB2[buf][n + 1]));
                yb        = ffma2(s2[n + 1], *(const ull*)&sC2[buf][n + 1], yb);
            }
            float2 yy = unpk2(ya);
            float2 yz = unpk2(yb);
            float2 gz = __half22float2(gzh);
            float g0 = (yy.x + yz.x) * gz.x;
            float g1 = (yy.y + yz.y) * gz.y;
            __half2 gh = __floats2half2_rn(g0, g1);
            *(__half2*)(gout + (size_t)t * 256 + c0) = gh;
        }

        rawh = nrawh; gzh = ngzh; dtA = ndtA;
    }
}

// =====================================================================
// combine: fully parallel RMS sums + rsqrt + pool + head
// =====================================================================
__global__ void __launch_bounds__(256)
combine_kernel(const float* __restrict__ norm_w,
               const float* __restrict__ head_b, float* __restrict__ out) {
    const int b = blockIdx.x;
    const int tid = threadIdx.x;
    const int lane = tid & 31, wid = tid >> 5;

    __shared__ float s_nwv[256];
    __shared__ float sred[8];

    s_nwv[tid] = norm_w[tid] * g_v[tid];
    __syncthreads();

    const __half* gp = g_gout + (size_t)b * NT * 256;
    float facc = 0.f;

    for (int t = wid; t < NT; t += 8) {
        const uint2* rowp = (const uint2*)(gp + (size_t)t * 256);
        uint2 u0 = rowp[2 * lane];
        uint2 u1 = rowp[2 * lane + 1];
        const float* nv = s_nwv + 8 * lane;
        float2 a = __half22float2(*(__half2*)&u0.x);
        float2 c = __half22float2(*(__half2*)&u0.y);
        float2 d = __half22float2(*(__half2*)&u1.x);
        float2 e = __half22float2(*(__half2*)&u1.y);
        float SS = a.x * a.x + a.y * a.y + c.x * c.x + c.y * c.y
                 + d.x * d.x + d.y * d.y + e.x * e.x + e.y * e.y;
        float P = a.x * nv[0] + a.y * nv[1] + c.x * nv[2] + c.y * nv[3]
                + d.x * nv[4] + d.y * nv[5] + e.x * nv[6] + e.y * nv[7];
        #pragma unroll
        for (int o = 16; o > 0; o >>= 1) {
            SS += __shfl_xor_sync(0xffffffffu, SS, o);
            P  += __shfl_xor_sync(0xffffffffu, P, o);
        }
        if (lane == 0)
            facc = fmaf(P, rsqrtf(SS * (1.f / 256.f) + EPSV), facc);
    }

    if (lane == 0) sred[wid] = facc;
    __syncthreads();
    if (tid == 0) {
        float tot = 0.f;
        #pragma unroll
        for (int w = 0; w < 8; w++) tot += sred[w];
        out[b] = tot * (1.f / (float)NT) + head_b[0];
    }
}

// =====================================================================
// launch
// =====================================================================
extern "C" void kernel_launch(void* const* d_in, const int* in_sizes, int n_in,
                              void* d_out, int out_size) {
    const float* x          = (const float*)d_in[0];
    const float* mixer_w    = (const float*)d_in[1];
    const float* mixer_b    = (const float*)d_in[2];
    const float* in_proj_w  = (const float*)d_in[3];
    const float* conv_w     = (const float*)d_in[4];
    const float* conv_b     = (const float*)d_in[5];
    const float* dt_bias    = (const float*)d_in[6];
    const float* A_log      = (const float*)d_in[7];
    const float* Dvec       = (const float*)d_in[8];
    const float* norm_w     = (const float*)d_in[9];
    const float* out_proj_w = (const float*)d_in[10];
    const float* head_w     = (const float*)d_in[11];
    const float* head_b     = (const float*)d_in[12];
    float* out = (float*)d_out;

    {
        int total = DPROJ * NCH + DPROJ + DINNER;
        prep1_kernel<<<(total + 255) / 256, 256>>>(in_proj_w, mixer_w, mixer_b,
                                                   out_proj_w, head_w);
    }
    {
        int total = NJC * TN * TK + 1152;
        prep2_kernel<<<(total + 255) / 256, 256>>>();
    }
    {
        cudaFuncSetAttribute(gemm_mma,
                             cudaFuncAttributeMaxDynamicSharedMemorySize, SMEM_SZ);
        dim3 grid(2, NJC, BSZ);
        gemm_mma<<<grid, 256, SMEM_SZ>>>(x, dt_bias, A_log);
    }
    scan_kernel<<<BSZ, 160>>>(conv_w, conv_b, Dvec);
    combine_kernel<<<BSZ, 256>>>(norm_w, head_b, out);
}

// round 12
// speedup vs baseline: 1.1087x; 1.1087x over previous
#include <cuda_runtime.h>
#include <cuda_fp16.h>
#include <cstdint>

// ---------------- model constants ----------------
#define BSZ      512
#define NCH      129
#define NT       250
#define DINNER   256
#define DSTATE   16
#define NHEADS   4
#define CONVDIM  288
#define DPROJ    548
#define EPSV     1e-5f
#define ROWH     544        // gz(256)+xBC raw(288) fp16 per row

// GEMM tiling
#define TM     128
#define TN     144
#define TK     128
#define NJC    4
#define NKK    8
#define PITCHB 272
#define SPITCH 148

// scan prefetch ring
#define RD     8            // ring depth (lookahead 7)

// ---------------- device scratch ----------------
__device__ float g_W[DPROJ * NCH];
__device__ float g_bias[DPROJ];
__device__ float g_v[DINNER];
__device__ __align__(16) __half g_zx[(size_t)BSZ * NT * ROWH];
__device__ __align__(16) float g_dtA[(size_t)BSZ * NT * 8];
__device__ __align__(16) __half g_gout[(size_t)BSZ * NT * 256];
__device__ __align__(16) __half g_Wh[NJC * TN * TK];
__device__ float g_Wcol[576];
__device__ float g_biasP[576];

// ---------------- GEMM smem layout (bytes) ----------------
#define SM_AH    0
#define SM_BH    34816
#define SM_X128  75776
#define SM_W128  76288
#define SM_BIAS  76864
#define SMEM_SZ  77440

// ---------------- packed f32x2 helpers ----------------
typedef unsigned long long ull;
__device__ __forceinline__ ull dup2(float v) {
    ull r; asm("mov.b64 %0, {%1, %1};" : "=l"(r) : "f"(v)); return r;
}
__device__ __forceinline__ ull pack2(float lo, float hi) {
    ull r; asm("mov.b64 %0, {%1, %2};" : "=l"(r) : "f"(lo), "f"(hi)); return r;
}
__device__ __forceinline__ ull ffma2(ull a, ull b, ull c) {
    ull d; asm("fma.rn.f32x2 %0, %1, %2, %3;" : "=l"(d) : "l"(a), "l"(b), "l"(c)); return d;
}
__device__ __forceinline__ ull fmul2(ull a, ull b) {
    ull d; asm("mul.rn.f32x2 %0, %1, %2;" : "=l"(d) : "l"(a), "l"(b)); return d;
}
__device__ __forceinline__ float2 unpk2(ull v) {
    float2 f; asm("mov.b64 {%0, %1}, %2;" : "=f"(f.x), "=f"(f.y) : "l"(v)); return f;
}

// ---------------- mma / ldmatrix / cp.async ----------------
__device__ __forceinline__ void mma16816(float* d, const uint32_t* a, const uint32_t* b) {
    asm volatile(
        "mma.sync.aligned.m16n8k16.row.col.f32.f16.f16.f32 "
        "{%0,%1,%2,%3}, {%4,%5,%6,%7}, {%8,%9}, {%0,%1,%2,%3};"
        : "+f"(d[0]), "+f"(d[1]), "+f"(d[2]), "+f"(d[3])
        : "r"(a[0]), "r"(a[1]), "r"(a[2]), "r"(a[3]), "r"(b[0]), "r"(b[1]));
}
__device__ __forceinline__ void ldsm4(uint32_t* r, uint32_t addr) {
    asm volatile("ldmatrix.sync.aligned.m8n8.x4.shared.b16 {%0,%1,%2,%3}, [%4];"
        : "=r"(r[0]), "=r"(r[1]), "=r"(r[2]), "=r"(r[3]) : "r"(addr));
}
__device__ __forceinline__ uint32_t smem_u32(const void* p) {
    uint32_t a;
    asm("{ .reg .u64 t; cvta.to.shared.u64 t, %1; cvt.u32.u64 %0, t; }" : "=r"(a) : "l"(p));
    return a;
}
#define CP_ASYNC4(sa, gp) asm volatile("cp.async.ca.shared.global [%0], [%1], 4;" :: "r"(sa), "l"(gp) : "memory")
#define CP_ASYNC8(sa, gp) asm volatile("cp.async.ca.shared.global [%0], [%1], 8;" :: "r"(sa), "l"(gp) : "memory")
#define CP_COMMIT()       asm volatile("cp.async.commit_group;" ::: "memory")
#define CP_WAIT6()        asm volatile("cp.async.wait_group 6;" ::: "memory")

// =====================================================================
// prep1: fused weights
// =====================================================================
__global__ void prep1_kernel(const float* __restrict__ in_proj_w,
                             const float* __restrict__ mixer_w,
                             const float* __restrict__ mixer_b,
                             const float* __restrict__ out_proj_w,
                             const float* __restrict__ head_w) {
    int idx = blockIdx.x * blockDim.x + threadIdx.x;
    const int NW = DPROJ * NCH;
    if (idx < NW) {
        int j = idx / NCH, c = idx - j * NCH;
        float a0 = 0.f, a1 = 0.f, a2 = 0.f, a3 = 0.f;
        #pragma unroll 8
        for (int d = 0; d < 128; d += 4) {
            a0 = fmaf(in_proj_w[j * 128 + d + 0], mixer_w[(d + 0) * NCH + c], a0);
            a1 = fmaf(in_proj_w[j * 128 + d + 1], mixer_w[(d + 1) * NCH + c], a1);
            a2 = fmaf(in_proj_w[j * 128 + d + 2], mixer_w[(d + 2) * NCH + c], a2);
            a3 = fmaf(in_proj_w[j * 128 + d + 3], mixer_w[(d + 3) * NCH + c], a3);
        }
        g_W[idx] = (a0 + a1) + (a2 + a3);
    } else if (idx < NW + DPROJ) {
        int j = idx - NW;
        float acc = 0.f;
        #pragma unroll 4
        for (int d = 0; d < 128; d++)
            acc = fmaf(in_proj_w[j * 128 + d], mixer_b[d], acc);
        g_bias[j] = acc;
    } else if (idx < NW + DPROJ + DINNER) {
        int i = idx - NW - DPROJ;
        float acc = 0.f;
        #pragma unroll 4
        for (int d = 0; d < 128; d++)
            acc = fmaf(out_proj_w[d * DINNER + i], head_w[d], acc);
        g_v[i] = acc;
    }
}

// =====================================================================
// prep2: W (k<128) -> fp16 chunk tiles [jc][n(144)][k(128)]
// =====================================================================
__global__ void prep2_kernel() {
    int idx = blockIdx.x * blockDim.x + threadIdx.x;
    const int NH = NJC * TN * TK;
    if (idx < NH) {
        int k = idx & 127;
        int t = idx >> 7;
        int n = t % TN;
        int jc = t / TN;
        int j = jc * TN + n;
        float val = (j < DPROJ) ? g_W[j * NCH + k] : 0.f;
        g_Wh[idx] = __float2half(val);
    } else if (idx < NH + 576) {
        int j = idx - NH;
        g_Wcol[j] = (j < DPROJ) ? g_W[j * NCH + 128] : 0.f;
    } else if (idx < NH + 1152) {
        int j = idx - NH - 576;
        g_biasP[j] = (j < DPROJ) ? g_bias[j] : 0.f;
    }
}

// =====================================================================
// gemm_mma: single-pass fp16 GEMM (R11, layout-fixed); epilogue applies
//   silu(z) + softplus/dA; writes fp16 gz/xBC + fp32 dt/dA
// =====================================================================
__global__ void __launch_bounds__(256, 2)
gemm_mma(const float* __restrict__ x,
         const float* __restrict__ dt_bias,
         const float* __restrict__ A_log) {
    extern __shared__ __align__(16) unsigned char sm[];
    const uint32_t sbase = smem_u32(sm);
    const int tid = threadIdx.x;
    const int wid = tid >> 5, lane = tid & 31;
    const int gid = lane >> 2, tig = lane & 3;
    const int tt = blockIdx.x, jc = blockIdx.y, b = blockIdx.z;
    const int t0 = tt * TM;

    {
        const unsigned char* src = (const unsigned char*)(g_Wh + (size_t)jc * (TN * TK));
        for (int i = tid; i < TN * 16; i += 256) {
            int n = i >> 4, q = i & 15;
            *(uint4*)(sm + SM_BH + n * PITCHB + q * 16) = *(const uint4*)(src + n * 256 + q * 16);
        }
    }
    {
        const float* xb = x + (size_t)b * (NCH * NT);
        for (int i = tid; i < 64 * TM; i += 256) {
            int cp = i >> 7, m = i & (TM - 1);
            int t = t0 + m;
            int c0 = 2 * cp;
            float v0 = (t < NT) ? xb[(size_t)c0 * NT + t] : 0.f;
            float v1 = (t < NT) ? xb[(size_t)(c0 + 1) * NT + t] : 0.f;
            uint32_t off = (uint32_t)m * PITCHB + (uint32_t)cp * 4;
            *(__half2*)(sm + SM_AH + off) = __half2{__float2half(v0), __float2half(v1)};
        }
    }
    if (tid < 128) {
        int t = t0 + tid;
        const float* xb = x + (size_t)b * (NCH * NT);
        *(float*)(sm + SM_X128 + tid * 4) = (t < NT) ? xb[(size_t)128 * NT + t] : 0.f;
    }
    for (int i = tid; i < TN; i += 256) {
        *(float*)(sm + SM_W128 + i * 4) = g_Wcol[jc * TN + i];
        *(float*)(sm + SM_BIAS + i * 4) = g_biasP[jc * TN + i];
    }
    __syncthreads();

    float acc[18][4];
    #pragma unroll
    for (int ni = 0; ni < 18; ni++)
        #pragma unroll
        for (int q = 0; q < 4; q++) acc[ni][q] = 0.f;

    const uint32_t aOff = (uint32_t)(wid * 16 + (lane & 15)) * PITCHB + (uint32_t)(lane >> 4) * 16;
    const uint32_t bOff = (uint32_t)(lane & 15) * PITCHB + (uint32_t)(lane >> 4) * 16;

    const uint32_t Ah = sbase + SM_AH + aOff;
    const uint32_t Bb = sbase + SM_BH + bOff;

    #pragma unroll
    for (int kk = 0; kk < NKK; kk++) {
        uint32_t ah[4];
        ldsm4(ah, Ah + kk * 32);
        #pragma unroll
        for (int q = 0; q < 9; q++) {
            uint32_t bb[4];
            ldsm4(bb, Bb + (uint32_t)(q * 16) * PITCHB + kk * 32);
            uint32_t f0[2] = { bb[0], bb[2] };
            uint32_t f1[2] = { bb[1], bb[3] };
            mma16816(acc[2 * q],     ah, f0);
            mma16816(acc[2 * q + 1], ah, f1);
        }
    }

    __syncthreads();
    float* stage = (float*)sm;
    {
        int r = wid * 16 + gid;
        #pragma unroll
        for (int ni = 0; ni < 18; ni++) {
            int c = ni * 8 + 2 * tig;
            *(float2*)(stage + r * SPITCH + c) = make_float2(acc[ni][0], acc[ni][1]);
            *(float2*)(stage + (r + 8) * SPITCH + c) = make_float2(acc[ni][2], acc[ni][3]);
        }
    }
    __syncthreads();

    const float* xs128 = (const float*)(sm + SM_X128);
    const float* sW = (const float*)(sm + SM_W128);
    const float* sBs = (const float*)(sm + SM_BIAS);
    for (int i = tid; i < TM * (TN / 4); i += 256) {
        int row = i / (TN / 4), q = i % (TN / 4);
        int t = t0 + row;
        int j = jc * TN + 4 * q;
        if (t >= NT) continue;
        const float* sp = stage + row * SPITCH + 4 * q;
        float xk = xs128[row];
        float o0 = fmaf(xk, sW[4 * q + 0], sp[0] + sBs[4 * q + 0]);
        float o1 = fmaf(xk, sW[4 * q + 1], sp[1] + sBs[4 * q + 1]);
        float o2 = fmaf(xk, sW[4 * q + 2], sp[2] + sBs[4 * q + 2]);
        float o3 = fmaf(xk, sW[4 * q + 3], sp[3] + sBs[4 * q + 3]);
        if (j + 3 < 256) {
            o0 = __fdividef(o0, 1.f + __expf(-o0));
            o1 = __fdividef(o1, 1.f + __expf(-o1));
            o2 = __fdividef(o2, 1.f + __expf(-o2));
            o3 = __fdividef(o3, 1.f + __expf(-o3));
            __half2 ha = __floats2half2_rn(o0, o1);
            __half2 hb = __floats2half2_rn(o2, o3);
            uint2 pk = { *(uint32_t*)&ha, *(uint32_t*)&hb };
            *(uint2*)(g_zx + ((size_t)b * NT + t) * ROWH + j) = pk;
        } else if (j + 3 < 544) {
            __half2 ha = __floats2half2_rn(o0, o1);
            __half2 hb = __floats2half2_rn(o2, o3);
            uint2 pk = { *(uint32_t*)&ha, *(uint32_t*)&hb };
            *(uint2*)(g_zx + ((size_t)b * NT + t) * ROWH + j) = pk;
        } else if (j == 544) {
            float ov[4] = { o0, o1, o2, o3 };
            float* dst = g_dtA + ((size_t)b * NT + t) * 8;
            float4 lo, hi;
            float r0 = ov[0] + dt_bias[0];
            float d0 = (r0 > 15.f) ? r0 : __logf(1.f + __expf(r0));
            lo.x = d0; lo.y = __expf(d0 * -__expf(A_log[0]));
            float r1 = ov[1] + dt_bias[1];
            float d1 = (r1 > 15.f) ? r1 : __logf(1.f + __expf(r1));
            lo.z = d1; lo.w = __expf(d1 * -__expf(A_log[1]));
            float r2 = ov[2] + dt_bias[2];
            float d2 = (r2 > 15.f) ? r2 : __logf(1.f + __expf(r2));
            hi.x = d2; hi.y = __expf(d2 * -__expf(A_log[2]));
            float r3 = ov[3] + dt_bias[3];
            float d3 = (r3 > 15.f) ? r3 : __logf(1.f + __expf(r3));
            hi.z = d3; hi.w = __expf(d3 * -__expf(A_log[3]));
            *(float4*)(dst) = lo;
            *(float4*)(dst + 4) = hi;
        }
    }
}

// =====================================================================
// scan: cp.async ring (depth 8, lookahead 7) — per-step load latency
//   exposure cut ~7x. Roles: tid<128 scan+conv, 128-143 B/C conv,
//   144-147 dt loader. One barrier per step.
// =====================================================================
__global__ void __launch_bounds__(160, 4)
scan_kernel(const float* __restrict__ conv_w, const float* __restrict__ conv_b,
            const float* __restrict__ Dp) {
    const int b = blockIdx.x;
    const int tid = threadIdx.x;
    const int c0 = 2 * tid;
    const int h = tid >> 5;

    __shared__ uint32_t sXBC[RD][144];
    __shared__ uint32_t sGZ[RD][128];
    __shared__ float    sDTA[RD][8];
    __shared__ __align__(8) float2 sB2[2][DSTATE];
    __shared__ __align__(8) float2 sC2[2][DSTATE];

    const bool isConv = (tid < 144);
    const bool isScan = (tid < 128);
    const bool isDt   = (tid >= 144 && tid < 148);

    ull wk0 = 0, wk1 = 0, wk2_ = 0, wk3 = 0, cb2 = 0;
    if (isConv) {
        wk0 = pack2(conv_w[c0 * 4 + 0], conv_w[(c0 + 1) * 4 + 0]);
        wk1 = pack2(conv_w[c0 * 4 + 1], conv_w[(c0 + 1) * 4 + 1]);
        wk2_ = pack2(conv_w[c0 * 4 + 2], conv_w[(c0 + 1) * 4 + 2]);
        wk3 = pack2(conv_w[c0 * 4 + 3], conv_w[(c0 + 1) * 4 + 3]);
        cb2 = pack2(conv_b[c0], conv_b[c0 + 1]);
    }
    ull h1 = 0ULL, h2 = 0ULL, h3 = 0ULL;

    ull D2 = 0ULL;
    if (isScan) D2 = dup2(Dp[h]);

    ull s2[DSTATE];
    #pragma unroll
    for (int n = 0; n < DSTATE; n++) s2[n] = 0ULL;

    const __half* zx = g_zx + (size_t)b * NT * ROWH;
    const float* dtp = g_dtA + (size_t)b * NT * 8;
    __half* gout = g_gout + (size_t)b * NT * 256;

    // per-thread smem target addresses
    uint32_t aXBC = isConv ? smem_u32(&sXBC[0][tid]) : 0;
    uint32_t aGZ  = isScan ? smem_u32(&sGZ[0][tid]) : 0;
    uint32_t aDTA = isDt   ? smem_u32(&sDTA[0][2 * (tid - 144)]) : 0;

    // prologue: steps 0..6, one group each
    #pragma unroll
    for (int d = 0; d < RD - 1; d++) {
        if (isConv) CP_ASYNC4(aXBC + d * 144 * 4, (const void*)(zx + (size_t)d * ROWH + 256 + c0));
        if (isScan) CP_ASYNC4(aGZ + d * 128 * 4, (const void*)(zx + (size_t)d * ROWH + c0));
        if (isDt)   CP_ASYNC8(aDTA + d * 8 * 4, (const void*)(dtp + (size_t)d * 8 + 2 * (tid - 144)));
        CP_COMMIT();
    }

    for (int t = 0; t < NT; t++) {
        const int slot = t & (RD - 1);
        const int buf = t & 1;

        CP_WAIT6();                      // step t's group resident

        // ---- conv + silu (reads own-thread cp.async data) ----
        float cs0 = 0.f, cs1 = 0.f;
        if (isConv) {
            uint32_t rawu = sXBC[slot][tid];
            float2 fr = __half22float2(*(const __half2*)&rawu);
            ull r2 = pack2(fr.x, fr.y);
            ull cv2 = ffma2(wk3, r2, ffma2(wk2_, h1, ffma2(wk1, h2, ffma2(wk0, h3, cb2))));
            h3 = h2; h2 = h1; h1 = r2;
            float2 cv = unpk2(cv2);
            cs0 = __fdividef(cv.x, 1.f + __expf(-cv.x));
            cs1 = __fdividef(cv.y, 1.f + __expf(-cv.y));
            if (tid >= 128) {
                if (tid < 136) {
                    int k = 2 * (tid - 128);
                    sB2[buf][k]     = make_float2(cs0, cs0);
                    sB2[buf][k + 1] = make_float2(cs1, cs1);
                } else {
                    int k = 2 * (tid - 136);
                    sC2[buf][k]     = make_float2(cs0, cs0);
                    sC2[buf][k + 1] = make_float2(cs1, cs1);
                }
            }
        }
        __syncthreads();                 // publish B/C conv + dtA for cross-thread reads

        // ---- state update + gate + store ----
        if (isScan) {
            float2 dtA = *(const float2*)&sDTA[slot][2 * h];
            uint32_t gzu = sGZ[slot][tid];
            float2 gz = __half22float2(*(const __half2*)&gzu);
            ull dA2 = dup2(dtA.y);
            ull dx2 = pack2(dtA.x * cs0, dtA.x * cs1);
            ull ya = fmul2(D2, pack2(cs0, cs1));
            ull yb = 0ULL;
            #pragma unroll
            for (int n = 0; n < DSTATE; n += 2) {
                s2[n]     = ffma2(s2[n],     dA2, fmul2(dx2, *(const ull*)&sB2[buf][n]));
                ya        = ffma2(s2[n],     *(const ull*)&sC2[buf][n], ya);
                s2[n + 1] = ffma2(s2[n + 1], dA2, fmul2(dx2, *(const ull*)&sB2[buf][n + 1]));
                yb        = ffma2(s2[n + 1], *(const ull*)&sC2[buf][n + 1], yb);
            }
            float2 yy = unpk2(ya);
            float2 yz = unpk2(yb);
            float g0 = (yy.x + yz.x) * gz.x;
            float g1 = (yy.y + yz.y) * gz.y;
            __half2 gh = __floats2half2_rn(g0, g1);
            *(__half2*)(gout + (size_t)t * 256 + c0) = gh;
        }

        // ---- issue prefetch for step t+7 (slot reused from iter t-1; safe:
        //      all reads of that slot preceded this iteration's barrier) ----
        {
            int s = t + RD - 1;
            if (s < NT) {
                int sl = s & (RD - 1);
                if (isConv) CP_ASYNC4(aXBC + sl * 144 * 4, (const void*)(zx + (size_t)s * ROWH + 256 + c0));
                if (isScan) CP_ASYNC4(aGZ + sl * 128 * 4, (const void*)(zx + (size_t)s * ROWH + c0));
                if (isDt)   CP_ASYNC8(aDTA + sl * 8 * 4, (const void*)(dtp + (size_t)s * 8 + 2 * (tid - 144)));
            }
            CP_COMMIT();                 // uniform group count (empty ok)
        }
    }
}

// =====================================================================
// combine: fully parallel RMS sums + rsqrt + pool + head
// =====================================================================
__global__ void __launch_bounds__(256)
combine_kernel(const float* __restrict__ norm_w,
               const float* __restrict__ head_b, float* __restrict__ out) {
    const int b = blockIdx.x;
    const int tid = threadIdx.x;
    const int lane = tid & 31, wid = tid >> 5;

    __shared__ float s_nwv[256];
    __shared__ float sred[8];

    s_nwv[tid] = norm_w[tid] * g_v[tid];
    __syncthreads();

    const __half* gp = g_gout + (size_t)b * NT * 256;
    float facc = 0.f;

    for (int t = wid; t < NT; t += 8) {
        const uint2* rowp = (const uint2*)(gp + (size_t)t * 256);
        uint2 u0 = rowp[2 * lane];
        uint2 u1 = rowp[2 * lane + 1];
        const float* nv = s_nwv + 8 * lane;
        float2 a = __half22float2(*(__half2*)&u0.x);
        float2 c = __half22float2(*(__half2*)&u0.y);
        float2 d = __half22float2(*(__half2*)&u1.x);
        float2 e = __half22float2(*(__half2*)&u1.y);
        float SS = a.x * a.x + a.y * a.y + c.x * c.x + c.y * c.y
                 + d.x * d.x + d.y * d.y + e.x * e.x + e.y * e.y;
        float P = a.x * nv[0] + a.y * nv[1] + c.x * nv[2] + c.y * nv[3]
                + d.x * nv[4] + d.y * nv[5] + e.x * nv[6] + e.y * nv[7];
        #pragma unroll
        for (int o = 16; o > 0; o >>= 1) {
            SS += __shfl_xor_sync(0xffffffffu, SS, o);
            P  += __shfl_xor_sync(0xffffffffu, P, o);
        }
        if (lane == 0)
            facc = fmaf(P, rsqrtf(SS * (1.f / 256.f) + EPSV), facc);
    }

    if (lane == 0) sred[wid] = facc;
    __syncthreads();
    if (tid == 0) {
        float tot = 0.f;
        #pragma unroll
        for (int w = 0; w < 8; w++) tot += sred[w];
        out[b] = tot * (1.f / (float)NT) + head_b[0];
    }
}

// =====================================================================
// launch
// =====================================================================
extern "C" void kernel_launch(void* const* d_in, const int* in_sizes, int n_in,
                              void* d_out, int out_size) {
    const float* x          = (const float*)d_in[0];
    const float* mixer_w    = (const float*)d_in[1];
    const float* mixer_b    = (const float*)d_in[2];
    const float* in_proj_w  = (const float*)d_in[3];
    const float* conv_w     = (const float*)d_in[4];
    const float* conv_b     = (const float*)d_in[5];
    const float* dt_bias    = (const float*)d_in[6];
    const float* A_log      = (const float*)d_in[7];
    const float* Dvec       = (const float*)d_in[8];
    const float* norm_w     = (const float*)d_in[9];
    const float* out_proj_w = (const float*)d_in[10];
    const float* head_w     = (const float*)d_in[11];
    const float* head_b     = (const float*)d_in[12];
    float* out = (float*)d_out;

    {
        int total = DPROJ * NCH + DPROJ + DINNER;
        prep1_kernel<<<(total + 255) / 256, 256>>>(in_proj_w, mixer_w, mixer_b,
                                                   out_proj_w, head_w);
    }
    {
        int total = NJC * TN * TK + 1152;
        prep2_kernel<<<(total + 255) / 256, 256>>>();
    }
    {
        cudaFuncSetAttribute(gemm_mma,
                             cudaFuncAttributeMaxDynamicSharedMemorySize, SMEM_SZ);
        dim3 grid(2, NJC, BSZ);
        gemm_mma<<<grid, 256, SMEM_SZ>>>(x, dt_bias, A_log);
    }
    scan_kernel<<<BSZ, 160>>>(conv_w, conv_b, Dvec);
    combine_kernel<<<BSZ, 256>>>(norm_w, head_b, out);
}